// round 15
// baseline (speedup 1.0000x reference)
#include <cuda_runtime.h>
#include <cuda_bf16.h>
#include <cstdint>

#define BATCH 512
#define NV 6890
#define N3 20670      // NV*3
#define NP 20736      // padded N: 162*128
#define KDIM 224      // 207 + 10 + 7 pad
#define NJ 24
#define J54 54
#define NSEG 32
#define SEGLEN 224    // 7*32 ; 32*224 = 7168 >= 6890
#define KC 16

typedef unsigned long long ull;

__constant__ int c_parent[23] = {0, 0, 0, 1, 2, 3, 4, 5, 6, 7, 8, 9,
                                 9, 9, 12, 13, 14, 16, 17, 18, 19, 20, 21};

// ---- scratch ----
__device__ float g_JM[NJ * 3 * 11];
__device__ __nv_bfloat16 g_Ab[BATCH * KDIM];      // A row-major [b][k] bf16
__device__ __nv_bfloat16 g_Wb[(size_t)NP * KDIM]; // W row-major [n][k] bf16
__device__ float g_Gc[BATCH * NJ * 12];
__device__ float g_vposed[BATCH * N3];
__device__ float g_part[NSEG * BATCH * J54 * 3];
__device__ int g_jmap64;

__device__ __forceinline__ void mma_bf16(float* c, const uint32_t* a, const uint32_t* b) {
    asm volatile(
        "mma.sync.aligned.m16n8k16.row.col.f32.bf16.bf16.f32 "
        "{%0,%1,%2,%3}, {%4,%5,%6,%7}, {%8,%9}, {%0,%1,%2,%3};\n"
        : "+f"(c[0]), "+f"(c[1]), "+f"(c[2]), "+f"(c[3])
        : "r"(a[0]), "r"(a[1]), "r"(a[2]), "r"(a[3]), "r"(b[0]), "r"(b[1]));
}

// ---- packed fp32x2 ----
__device__ __forceinline__ ull pk2(float x, float y) {
    ull r;
    asm("mov.b64 %0, {%1, %2};" : "=l"(r) : "f"(x), "f"(y));
    return r;
}
__device__ __forceinline__ void upk2(ull v, float& x, float& y) {
    asm("mov.b64 {%0, %1}, %2;" : "=f"(x), "=f"(y) : "l"(v));
}
__device__ __forceinline__ ull ffma2(ull a, ull b, ull c) {
    ull r;
    asm("fma.rn.f32x2 %0, %1, %2, %3;" : "=l"(r) : "l"(a), "l"(b), "l"(c));
    return r;
}

__device__ __forceinline__ const float* reg_row(int r, const float* Jreg,
                                                const float* Jspin, const float* Jextra) {
    return (r < 24) ? (Jreg + r * NV)
         : (r < 45) ? (Jspin + (r - 24) * NV)
                    : (Jextra + (r - 45) * NV);
}

// ============================================================================
// prep: blocks [0, NP/8) pack W bf16; next 72 blocks compute g_JM; last block sniffs jmap
// ============================================================================
__global__ void __launch_bounds__(256) prep_kernel(const float* __restrict__ posedirs,
                                                   const float* __restrict__ shapedirs,
                                                   const float* __restrict__ Jreg,
                                                   const float* __restrict__ vtemp,
                                                   const int* __restrict__ jmap) {
    int t = threadIdx.x;
    if (blockIdx.x < NP / 8) {
        int n0 = blockIdx.x * 8;
        if (t < KDIM) {
#pragma unroll
            for (int r = 0; r < 8; r++) {
                int n = n0 + r;
                float v = 0.f;
                if (n < N3) {
                    if (t < 207)      v = posedirs[(size_t)n * 207 + t];
                    else if (t < 217) v = shapedirs[n * 10 + (t - 207)];
                }
                g_Wb[(size_t)n * KDIM + t] = __float2bfloat16(v);
            }
        }
    } else if (blockIdx.x < NP / 8 + 72) {
        int blk = blockIdx.x - NP / 8;
        int j = blk / 3, d = blk % 3;
        float acc[11];
#pragma unroll
        for (int k = 0; k < 11; k++) acc[k] = 0.f;
        const float* reg = Jreg + j * NV;
        for (int v = t; v < NV; v += 256) {
            float r = reg[v];
            const float* sd = shapedirs + (v * 3 + d) * 10;
#pragma unroll
            for (int k = 0; k < 10; k++) acc[k] += r * sd[k];
            acc[10] += r * vtemp[v * 3 + d];
        }
        __shared__ float red[256];
        for (int k = 0; k < 11; k++) {
            red[t] = acc[k];
            __syncthreads();
            for (int s = 128; s > 0; s >>= 1) {
                if (t < s) red[t] += red[t + s];
                __syncthreads();
            }
            if (t == 0) g_JM[(j * 3 + d) * 11 + k] = red[0];
            __syncthreads();
        }
    } else {
        if (t < 32) {
            int bad = (t < 24 && jmap[2 * t + 1] != 0) ? 1 : 0;
            unsigned m = __ballot_sync(0xffffffff, bad);
            if (t == 0) g_jmap64 = (m == 0) ? 1 : 0;
        }
    }
}

// ============================================================================
// pose: 4 batches per block; rodrigues, chain, Gc; writes bf16 A rows
// ============================================================================
__global__ void __launch_bounds__(128) pose_kernel(const float* __restrict__ pose,
                                                   const float* __restrict__ beta) {
    int w = threadIdx.x >> 5, t = threadIdx.x & 31;
    int b = blockIdx.x * 4 + w;
    __shared__ float sR[4][NJ][9];
    __shared__ float sJ[4][NJ][3];
    __shared__ float sA[4][NJ][12];

    if (t < NJ) {
        float rx = pose[b * 72 + 3 * t + 0];
        float ry = pose[b * 72 + 3 * t + 1];
        float rz = pose[b * 72 + 3 * t + 2];
        float th = sqrtf(rx * rx + ry * ry + rz * rz);
        float inv = 1.f / fmaxf(th, 1e-8f);
        float kx = rx * inv, ky = ry * inv, kz = rz * inv;
        float s = sinf(th), c = cosf(th), C = 1.f - c;
        float kn2 = kx * kx + ky * ky + kz * kz;
        float R[9];
        R[0] = 1.f + C * (kx * kx - kn2);
        R[1] = -s * kz + C * kx * ky;
        R[2] = s * ky + C * kx * kz;
        R[3] = s * kz + C * ky * kx;
        R[4] = 1.f + C * (ky * ky - kn2);
        R[5] = -s * kx + C * ky * kz;
        R[6] = -s * ky + C * kz * kx;
        R[7] = s * kx + C * kz * ky;
        R[8] = 1.f + C * (kz * kz - kn2);
#pragma unroll
        for (int e = 0; e < 9; e++) sR[w][t][e] = R[e];
        if (t >= 1) {
            __nv_bfloat16* dst = g_Ab + b * KDIM + (t - 1) * 9;
#pragma unroll
            for (int e = 0; e < 9; e++) {
                float val = R[e] - ((e == 0 || e == 4 || e == 8) ? 1.f : 0.f);
                dst[e] = __float2bfloat16(val);
            }
        }
#pragma unroll
        for (int d = 0; d < 3; d++) {
            const float* m = g_JM + (t * 3 + d) * 11;
            float val = m[10];
#pragma unroll
            for (int k = 0; k < 10; k++) val += m[k] * beta[b * 10 + k];
            sJ[w][t][d] = val;
        }
    }
    if (t == 0) {
#pragma unroll
        for (int k = 0; k < 10; k++)
            g_Ab[b * KDIM + 207 + k] = __float2bfloat16(beta[b * 10 + k]);
#pragma unroll
        for (int k = 217; k < KDIM; k++)
            g_Ab[b * KDIM + k] = __float2bfloat16(0.f);
    }
    __syncwarp();
    if (t == 0) {
#pragma unroll
        for (int e = 0; e < 9; e++) sA[w][0][(e / 3) * 4 + (e % 3)] = sR[w][0][e];
        sA[w][0][3] = sJ[w][0][0]; sA[w][0][7] = sJ[w][0][1]; sA[w][0][11] = sJ[w][0][2];
        for (int i = 1; i < NJ; i++) {
            int p = c_parent[i - 1];
            float lt0 = sJ[w][i][0] - sJ[w][p][0];
            float lt1 = sJ[w][i][1] - sJ[w][p][1];
            float lt2 = sJ[w][i][2] - sJ[w][p][2];
            for (int r = 0; r < 3; r++) {
                float p0 = sA[w][p][r * 4 + 0], p1 = sA[w][p][r * 4 + 1];
                float p2 = sA[w][p][r * 4 + 2], p3 = sA[w][p][r * 4 + 3];
                for (int cc = 0; cc < 3; cc++)
                    sA[w][i][r * 4 + cc] = p0 * sR[w][i][0 * 3 + cc] + p1 * sR[w][i][1 * 3 + cc] + p2 * sR[w][i][2 * 3 + cc];
                sA[w][i][r * 4 + 3] = p0 * lt0 + p1 * lt1 + p2 * lt2 + p3;
            }
        }
    }
    __syncwarp();
    if (t < NJ) {
        float j0 = sJ[w][t][0], j1 = sJ[w][t][1], j2 = sJ[w][t][2];
        float* dst = g_Gc + (b * NJ + t) * 12;
#pragma unroll
        for (int r = 0; r < 3; r++) {
            float a0 = sA[w][t][r * 4 + 0], a1 = sA[w][t][r * 4 + 1];
            float a2 = sA[w][t][r * 4 + 2], a3 = sA[w][t][r * 4 + 3];
            dst[r * 4 + 0] = a0; dst[r * 4 + 1] = a1; dst[r * 4 + 2] = a2;
            dst[r * 4 + 3] = a3 - (a0 * j0 + a1 * j1 + a2 * j2);
        }
    }
}

// ============================================================================
// GEMM bf16 m16n8k16: v_posed = A @ W^T + vtemp.
// KC=16, 14 stages, 4 smem buffers, prefetch distance 3 (hides DRAM latency).
// ============================================================================
__global__ void __launch_bounds__(256, 2) gemm_bf16_kernel(const float* __restrict__ vtemp) {
    __shared__ __align__(16) __nv_bfloat16 As[4][128][24];
    __shared__ __align__(16) __nv_bfloat16 Bs[4][128][24];
    int tid = threadIdx.x;
    int lane = tid & 31, wid = tid >> 5;
    int warp_m = wid & 1, warp_n = wid >> 1;
    int gq = lane >> 2, tq = lane & 3;
    int m0 = blockIdx.x * 128;
    int n0 = blockIdx.y * 128;

    float acc[4][4][4];
#pragma unroll
    for (int mt = 0; mt < 4; mt++)
#pragma unroll
        for (int nt = 0; nt < 4; nt++)
#pragma unroll
            for (int i = 0; i < 4; i++) acc[mt][nt][i] = 0.f;

    const int NSTAGE = KDIM / KC;  // 14
    const int mrow = tid >> 1, hh = tid & 1;

#define LOAD_STAGE(s)                                                                 \
    {                                                                                 \
        int k0 = (s) * KC;                                                            \
        int buf = (s) & 3;                                                            \
        unsigned da = (unsigned)__cvta_generic_to_shared(&As[buf][mrow][hh * 8]);     \
        const __nv_bfloat16* sa = g_Ab + (m0 + mrow) * KDIM + k0 + hh * 8;            \
        asm volatile("cp.async.cg.shared.global [%0], [%1], 16;" ::"r"(da), "l"(sa)); \
        unsigned db = (unsigned)__cvta_generic_to_shared(&Bs[buf][mrow][hh * 8]);     \
        const __nv_bfloat16* sb = g_Wb + (size_t)(n0 + mrow) * KDIM + k0 + hh * 8;    \
        asm volatile("cp.async.cg.shared.global [%0], [%1], 16;" ::"r"(db), "l"(sb)); \
        asm volatile("cp.async.commit_group;");                                       \
    }

    LOAD_STAGE(0);
    LOAD_STAGE(1);
    LOAD_STAGE(2);
    for (int s = 0; s < NSTAGE; s++) {
        if (s <= NSTAGE - 3) {
            asm volatile("cp.async.wait_group 2;");
        } else if (s == NSTAGE - 2) {
            asm volatile("cp.async.wait_group 1;");
        } else {
            asm volatile("cp.async.wait_group 0;");
        }
        __syncthreads();
        if (s + 3 < NSTAGE) LOAD_STAGE(s + 3);
        int buf = s & 3;
        const uint32_t* As32 = (const uint32_t*)&As[buf][0][0];
        const uint32_t* Bs32 = (const uint32_t*)&Bs[buf][0][0];
        uint32_t af[4][4], bf[4][2];
#pragma unroll
        for (int mt = 0; mt < 4; mt++) {
            int r = warp_m * 64 + mt * 16 + gq;
            af[mt][0] = As32[r * 12 + tq];
            af[mt][1] = As32[(r + 8) * 12 + tq];
            af[mt][2] = As32[r * 12 + 4 + tq];
            af[mt][3] = As32[(r + 8) * 12 + 4 + tq];
        }
#pragma unroll
        for (int nt = 0; nt < 4; nt++) {
            int cn = warp_n * 32 + nt * 8 + gq;
            bf[nt][0] = Bs32[cn * 12 + tq];
            bf[nt][1] = Bs32[cn * 12 + 4 + tq];
        }
#pragma unroll
        for (int mt = 0; mt < 4; mt++)
#pragma unroll
            for (int nt = 0; nt < 4; nt++)
                mma_bf16(acc[mt][nt], af[mt], bf[nt]);
        __syncthreads();
    }

#pragma unroll
    for (int mt = 0; mt < 4; mt++) {
        int row = m0 + warp_m * 64 + mt * 16 + gq;
#pragma unroll
        for (int nt = 0; nt < 4; nt++) {
            int cn = n0 + warp_n * 32 + nt * 8 + 2 * tq;
            if (cn < N3) {
                float2 vt = *(const float2*)(vtemp + cn);
                float2 o0 = {acc[mt][nt][0] + vt.x, acc[mt][nt][1] + vt.y};
                float2 o1 = {acc[mt][nt][2] + vt.x, acc[mt][nt][3] + vt.y};
                *(float2*)(g_vposed + (size_t)row * N3 + cn) = o0;
                *(float2*)(g_vposed + (size_t)(row + 8) * N3 + cn) = o1;
            }
        }
    }
#undef LOAD_STAGE
}

// ============================================================================
// skin (r11/r14 proven): 2 verts/thread x 16 batches (8 pairs) per block,
// T-matrix accumulation, software-pipelined vposed loads.
// ============================================================================
__global__ void __launch_bounds__(128) skin_kernel(const float* __restrict__ weights,
                                                   float* __restrict__ out) {
    __shared__ __align__(16) ull sGc2[8 * 288];
    int b0 = blockIdx.y * 16;
    int t = threadIdx.x;
    int vA = blockIdx.x * 256 + t;        // grid.x = 27
    int vB = vA + 128;
    for (int idx = t; idx < 8 * 288; idx += 128) {
        int p = idx / 288, e = idx % 288;
        sGc2[idx] = pk2(g_Gc[(size_t)(b0 + 2 * p) * 288 + e],
                        g_Gc[(size_t)(b0 + 2 * p + 1) * 288 + e]);
    }
    __syncthreads();
    bool okA = vA < NV, okB = vB < NV;
    float wA[NJ], wB[NJ];
    {
        const float4* wa = (const float4*)(weights + (size_t)vA * NJ);
        const float4* wb = (const float4*)(weights + (size_t)vB * NJ);
#pragma unroll
        for (int i = 0; i < 6; i++) {
            float4 x = okA ? wa[i] : make_float4(0.f, 0.f, 0.f, 0.f);
            wA[4 * i + 0] = x.x; wA[4 * i + 1] = x.y; wA[4 * i + 2] = x.z; wA[4 * i + 3] = x.w;
            float4 y = okB ? wb[i] : make_float4(0.f, 0.f, 0.f, 0.f);
            wB[4 * i + 0] = y.x; wB[4 * i + 1] = y.y; wB[4 * i + 2] = y.z; wB[4 * i + 3] = y.w;
        }
    }
    float curA[6], curB[6], nxtA[6], nxtB[6];
#pragma unroll
    for (int i = 0; i < 6; i++) { curA[i] = 0.f; curB[i] = 0.f; nxtA[i] = 0.f; nxtB[i] = 0.f; }
    {
        const float* va = g_vposed + (size_t)b0 * N3;
        const float* vb = va + N3;
        if (okA) {
            curA[0] = va[vA * 3 + 0]; curA[1] = va[vA * 3 + 1]; curA[2] = va[vA * 3 + 2];
            curA[3] = vb[vA * 3 + 0]; curA[4] = vb[vA * 3 + 1]; curA[5] = vb[vA * 3 + 2];
        }
        if (okB) {
            curB[0] = va[vB * 3 + 0]; curB[1] = va[vB * 3 + 1]; curB[2] = va[vB * 3 + 2];
            curB[3] = vb[vB * 3 + 0]; curB[4] = vb[vB * 3 + 1]; curB[5] = vb[vB * 3 + 2];
        }
    }
#pragma unroll 1
    for (int p = 0; p < 8; p++) {
        if (p < 7) {
            const float* va = g_vposed + (size_t)(b0 + 2 * p + 2) * N3;
            const float* vb = va + N3;
            if (okA) {
                nxtA[0] = va[vA * 3 + 0]; nxtA[1] = va[vA * 3 + 1]; nxtA[2] = va[vA * 3 + 2];
                nxtA[3] = vb[vA * 3 + 0]; nxtA[4] = vb[vA * 3 + 1]; nxtA[5] = vb[vA * 3 + 2];
            }
            if (okB) {
                nxtB[0] = va[vB * 3 + 0]; nxtB[1] = va[vB * 3 + 1]; nxtB[2] = va[vB * 3 + 2];
                nxtB[3] = vb[vB * 3 + 0]; nxtB[4] = vb[vB * 3 + 1]; nxtB[5] = vb[vB * 3 + 2];
            }
        }
        ull TA[12], TB[12];
#pragma unroll
        for (int c = 0; c < 12; c++) { TA[c] = 0ull; TB[c] = 0ull; }
        const ulonglong2* gc = (const ulonglong2*)(sGc2 + p * 288);
#pragma unroll
        for (int j = 0; j < NJ; j++) {
            ull wa2 = pk2(wA[j], wA[j]);
            ull wb2 = pk2(wB[j], wB[j]);
#pragma unroll
            for (int i = 0; i < 6; i++) {
                ulonglong2 g2 = gc[j * 6 + i];
                TA[2 * i + 0] = ffma2(wa2, g2.x, TA[2 * i + 0]);
                TA[2 * i + 1] = ffma2(wa2, g2.y, TA[2 * i + 1]);
                TB[2 * i + 0] = ffma2(wb2, g2.x, TB[2 * i + 0]);
                TB[2 * i + 1] = ffma2(wb2, g2.y, TB[2 * i + 1]);
            }
        }
        int ba = b0 + 2 * p, bb = ba + 1;
        if (okA) {
            ull px = pk2(curA[0], curA[3]);
            ull py = pk2(curA[1], curA[4]);
            ull pz = pk2(curA[2], curA[5]);
            float* oa = out + (size_t)ba * N3 + vA * 3;
            float* ob = out + (size_t)bb * N3 + vA * 3;
#pragma unroll
            for (int r = 0; r < 3; r++) {
                ull o2 = ffma2(TA[4 * r + 0], px,
                         ffma2(TA[4 * r + 1], py,
                         ffma2(TA[4 * r + 2], pz, TA[4 * r + 3])));
                float xa, xb;
                upk2(o2, xa, xb);
                oa[r] = xa; ob[r] = xb;
            }
        }
        if (okB) {
            ull px = pk2(curB[0], curB[3]);
            ull py = pk2(curB[1], curB[4]);
            ull pz = pk2(curB[2], curB[5]);
            float* oa = out + (size_t)ba * N3 + vB * 3;
            float* ob = out + (size_t)bb * N3 + vB * 3;
#pragma unroll
            for (int r = 0; r < 3; r++) {
                ull o2 = ffma2(TB[4 * r + 0], px,
                         ffma2(TB[4 * r + 1], py,
                         ffma2(TB[4 * r + 2], pz, TB[4 * r + 3])));
                float xa, xb;
                upk2(o2, xa, xb);
                oa[r] = xa; ob[r] = xb;
            }
        }
#pragma unroll
        for (int i = 0; i < 6; i++) { curA[i] = nxtA[i]; curB[i] = nxtB[i]; }
    }
}

// ============================================================================
// joints: 32 batches/block (16 pairs), 4 joints/thread, grid (16, 32),
// reg-prefetch pipeline. Regressor tile stored PRE-PACKED (ull) in smem:
// inner loop = 2 LDS.128 + 3 LDS.64 + 12 ffma2, no per-iter pk2 movs.
// ============================================================================
__global__ void __launch_bounds__(256) joints_kernel(const float* __restrict__ Jreg,
                                                     const float* __restrict__ Jspin,
                                                     const float* __restrict__ Jextra,
                                                     const float* __restrict__ outv) {
    __shared__ __align__(16) ull sreg2[32 * 70];  // [vv][j] packed (val,val), pad 70
    __shared__ __align__(16) ull sv2[32 * 48];
    float* svh = (float*)sv2;
    int b0 = blockIdx.x * 32;   // grid.x = 16
    int seg = blockIdx.y;       // grid.y = 32
    int tid = threadIdx.x;
    int tx = tid & 15, ty = tid >> 4;  // tx: pair 0..15, ty: 0..15 -> 4 joints
    int j0 = ty * 4;
    ull acc2[4][3];
#pragma unroll
    for (int i = 0; i < 4; i++)
#pragma unroll
        for (int d = 0; d < 3; d++) acc2[i][d] = 0ull;

    float rga[8];
    float2 sva[6];
    int kbeg = seg * SEGLEN;

#define PREFETCH_TILE(k0)                                                        \
    {                                                                            \
        _Pragma("unroll")                                                        \
        for (int i = 0; i < 8; i++) {                                            \
            int idx = tid + i * 256;                                             \
            int j = idx >> 5, vv = idx & 31;                                     \
            int gk = (k0) + vv;                                                  \
            float val = 0.f;                                                     \
            if (j < J54 && gk < NV) val = reg_row(j, Jreg, Jspin, Jextra)[gk];   \
            rga[i] = val;                                                        \
        }                                                                        \
        _Pragma("unroll")                                                        \
        for (int q = 0; q < 6; q++) {                                            \
            int idx = tid + q * 256;                                             \
            int pr = idx / 96, e = idx % 96;                                     \
            int half = e / 48, r2 = e % 48;                                      \
            sva[q] = *(const float2*)(outv + (size_t)(b0 + 2 * pr + half) * N3   \
                                       + (k0) * 3 + r2 * 2);                     \
        }                                                                        \
    }

#define COMMIT_TILE()                                                            \
    {                                                                            \
        _Pragma("unroll")                                                        \
        for (int i = 0; i < 8; i++) {                                            \
            int idx = tid + i * 256;                                             \
            sreg2[(idx & 31) * 70 + (idx >> 5)] = pk2(rga[i], rga[i]);           \
        }                                                                        \
        _Pragma("unroll")                                                        \
        for (int q = 0; q < 6; q++) {                                            \
            int idx = tid + q * 256;                                             \
            int pr = idx / 96, e = idx % 96;                                     \
            int half = e / 48, r2 = e % 48;                                      \
            int rem = r2 * 2;                                                    \
            int f0 = rem / 3, d0 = rem % 3;                                      \
            int f1 = (rem + 1) / 3, d1 = (rem + 1) % 3;                          \
            svh[(f0 * 48 + pr * 3 + d0) * 2 + half] = sva[q].x;                  \
            svh[(f1 * 48 + pr * 3 + d1) * 2 + half] = sva[q].y;                  \
        }                                                                        \
    }

    PREFETCH_TILE(kbeg);

    for (int k0 = kbeg; k0 < kbeg + SEGLEN; k0 += 32) {
        COMMIT_TILE();
        __syncthreads();
        int kn = k0 + 32;
        if (kn < kbeg + SEGLEN) PREFETCH_TILE(kn);
#pragma unroll
        for (int vv = 0; vv < 32; vv++) {
            ulonglong2 a01 = *(const ulonglong2*)&sreg2[vv * 70 + j0];
            ulonglong2 a23 = *(const ulonglong2*)&sreg2[vv * 70 + j0 + 2];
            ull bx = sv2[vv * 48 + tx * 3 + 0];
            ull by = sv2[vv * 48 + tx * 3 + 1];
            ull bz = sv2[vv * 48 + tx * 3 + 2];
            acc2[0][0] = ffma2(a01.x, bx, acc2[0][0]);
            acc2[0][1] = ffma2(a01.x, by, acc2[0][1]);
            acc2[0][2] = ffma2(a01.x, bz, acc2[0][2]);
            acc2[1][0] = ffma2(a01.y, bx, acc2[1][0]);
            acc2[1][1] = ffma2(a01.y, by, acc2[1][1]);
            acc2[1][2] = ffma2(a01.y, bz, acc2[1][2]);
            acc2[2][0] = ffma2(a23.x, bx, acc2[2][0]);
            acc2[2][1] = ffma2(a23.x, by, acc2[2][1]);
            acc2[2][2] = ffma2(a23.x, bz, acc2[2][2]);
            acc2[3][0] = ffma2(a23.y, bx, acc2[3][0]);
            acc2[3][1] = ffma2(a23.y, by, acc2[3][1]);
            acc2[3][2] = ffma2(a23.y, bz, acc2[3][2]);
        }
        __syncthreads();
    }
#undef PREFETCH_TILE
#undef COMMIT_TILE

    int ba = b0 + 2 * tx, bb2 = ba + 1;
#pragma unroll
    for (int i = 0; i < 4; i++) {
        int j = j0 + i;
        if (j < J54) {
#pragma unroll
            for (int d = 0; d < 3; d++) {
                float xa, xb;
                upk2(acc2[i][d], xa, xb);
                g_part[((size_t)(seg * BATCH + ba) * J54 + j) * 3 + d] = xa;
                g_part[((size_t)(seg * BATCH + bb2) * J54 + j) * 3 + d] = xb;
            }
        }
    }
}

// ============================================================================
// finalize: sum partials, pelvis, write joints & pelvis, shift vertices
// ============================================================================
__global__ void __launch_bounds__(256) finalize_kernel(const int* __restrict__ jmap,
                                                       float* __restrict__ out) {
    int b = blockIdx.x, t = threadIdx.x;
    __shared__ float jall[J54 * 3];
    __shared__ float pel[3];
    int is64 = g_jmap64;
    if (t < 162) {
        float s = 0.f;
        for (int seg = 0; seg < NSEG; seg++)
            s += g_part[(size_t)(seg * BATCH + b) * (J54 * 3) + t];
        jall[t] = s;
    }
    __syncthreads();
    if (t < 3) {
        int a = is64 ? jmap[2 * 27] : jmap[27];
        int c = is64 ? jmap[2 * 28] : jmap[28];
        float p = 0.5f * (jall[a * 3 + t] + jall[c * 3 + t]);
        pel[t] = p;
        out[(size_t)BATCH * N3 + (size_t)BATCH * 147 + b * 3 + t] = p;
    }
    __syncthreads();
    if (t < 147) {
        int i = t / 3, d = t % 3;
        int j = is64 ? jmap[2 * i] : jmap[i];
        out[(size_t)BATCH * N3 + b * 147 + t] = jall[j * 3 + d] - pel[d];
    }
    float p0 = pel[0], p1 = pel[1], p2 = pel[2];
    float* vb = out + (size_t)b * N3;
    for (int p = t; p < N3 / 2; p += 256) {
        int idx = 2 * p;
        int d0 = idx % 3;
        float2 v = *(float2*)(vb + idx);
        v.x -= (d0 == 0) ? p0 : (d0 == 1) ? p1 : p2;
        int d1 = (d0 + 1 == 3) ? 0 : d0 + 1;
        v.y -= (d1 == 0) ? p0 : (d1 == 1) ? p1 : p2;
        *(float2*)(vb + idx) = v;
    }
}

// ============================================================================
extern "C" void kernel_launch(void* const* d_in, const int* in_sizes, int n_in,
                              void* d_out, int out_size) {
    const float* pose      = (const float*)d_in[0];
    const float* beta      = (const float*)d_in[1];
    const float* vtemp     = (const float*)d_in[2];
    const float* shapedirs = (const float*)d_in[3];
    const float* posedirs  = (const float*)d_in[4];
    const float* weights   = (const float*)d_in[5];
    const float* Jreg      = (const float*)d_in[6];
    const float* Jspin     = (const float*)d_in[7];
    const float* Jextra    = (const float*)d_in[8];
    const int* jmap        = (const int*)d_in[10];
    float* out = (float*)d_out;

    prep_kernel<<<NP / 8 + 73, 256>>>(posedirs, shapedirs, Jreg, vtemp, jmap); // 0
    pose_kernel<<<BATCH / 4, 128>>>(pose, beta);                               // 1
    gemm_bf16_kernel<<<dim3(BATCH / 128, NP / 128), 256>>>(vtemp);             // 2
    skin_kernel<<<dim3(27, BATCH / 16), 128>>>(weights, out);                  // 3 <- profiled
    joints_kernel<<<dim3(BATCH / 32, NSEG), 256>>>(Jreg, Jspin, Jextra, out);  // 4
    finalize_kernel<<<BATCH, 256>>>(jmap, out);                                // 5
}

// round 16
// speedup vs baseline: 1.0892x; 1.0892x over previous
#include <cuda_runtime.h>
#include <cuda_bf16.h>
#include <cstdint>

#define BATCH 512
#define NV 6890
#define N3 20670      // NV*3
#define NP 20736      // padded N: 162*128
#define KDIM 224      // 207 + 10 + 7 pad
#define NJ 24
#define J54 54
#define NSEG 32
#define SEGLEN 224    // 7*32 ; 32*224 = 7168 >= 6890
#define KC 32

typedef unsigned long long ull;

__constant__ int c_parent[23] = {0, 0, 0, 1, 2, 3, 4, 5, 6, 7, 8, 9,
                                 9, 9, 12, 13, 14, 16, 17, 18, 19, 20, 21};

// ---- scratch ----
__device__ float g_JM[NJ * 3 * 11];
__device__ __nv_bfloat16 g_Ab[BATCH * KDIM];      // A row-major [b][k] bf16
__device__ __nv_bfloat16 g_Wb[(size_t)NP * KDIM]; // W row-major [n][k] bf16
__device__ float g_Gc[BATCH * NJ * 12];
__device__ float g_vposed[BATCH * N3];
__device__ float g_part[NSEG * BATCH * J54 * 3];
__device__ int g_jmap64;

__device__ __forceinline__ void mma_bf16(float* c, const uint32_t* a, const uint32_t* b) {
    asm volatile(
        "mma.sync.aligned.m16n8k16.row.col.f32.bf16.bf16.f32 "
        "{%0,%1,%2,%3}, {%4,%5,%6,%7}, {%8,%9}, {%0,%1,%2,%3};\n"
        : "+f"(c[0]), "+f"(c[1]), "+f"(c[2]), "+f"(c[3])
        : "r"(a[0]), "r"(a[1]), "r"(a[2]), "r"(a[3]), "r"(b[0]), "r"(b[1]));
}

// ---- packed fp32x2 ----
__device__ __forceinline__ ull pk2(float x, float y) {
    ull r;
    asm("mov.b64 %0, {%1, %2};" : "=l"(r) : "f"(x), "f"(y));
    return r;
}
__device__ __forceinline__ void upk2(ull v, float& x, float& y) {
    asm("mov.b64 {%0, %1}, %2;" : "=f"(x), "=f"(y) : "l"(v));
}
__device__ __forceinline__ ull ffma2(ull a, ull b, ull c) {
    ull r;
    asm("fma.rn.f32x2 %0, %1, %2, %3;" : "=l"(r) : "l"(a), "l"(b), "l"(c));
    return r;
}

__device__ __forceinline__ const float* reg_row(int r, const float* Jreg,
                                                const float* Jspin, const float* Jextra) {
    return (r < 24) ? (Jreg + r * NV)
         : (r < 45) ? (Jspin + (r - 24) * NV)
                    : (Jextra + (r - 45) * NV);
}

// ============================================================================
// prep: blocks [0, NP/8) pack W bf16; next 72 blocks compute g_JM; last block sniffs jmap
// ============================================================================
__global__ void __launch_bounds__(256) prep_kernel(const float* __restrict__ posedirs,
                                                   const float* __restrict__ shapedirs,
                                                   const float* __restrict__ Jreg,
                                                   const float* __restrict__ vtemp,
                                                   const int* __restrict__ jmap) {
    int t = threadIdx.x;
    if (blockIdx.x < NP / 8) {
        int n0 = blockIdx.x * 8;
        if (t < KDIM) {
#pragma unroll
            for (int r = 0; r < 8; r++) {
                int n = n0 + r;
                float v = 0.f;
                if (n < N3) {
                    if (t < 207)      v = posedirs[(size_t)n * 207 + t];
                    else if (t < 217) v = shapedirs[n * 10 + (t - 207)];
                }
                g_Wb[(size_t)n * KDIM + t] = __float2bfloat16(v);
            }
        }
    } else if (blockIdx.x < NP / 8 + 72) {
        int blk = blockIdx.x - NP / 8;
        int j = blk / 3, d = blk % 3;
        float acc[11];
#pragma unroll
        for (int k = 0; k < 11; k++) acc[k] = 0.f;
        const float* reg = Jreg + j * NV;
        for (int v = t; v < NV; v += 256) {
            float r = reg[v];
            const float* sd = shapedirs + (v * 3 + d) * 10;
#pragma unroll
            for (int k = 0; k < 10; k++) acc[k] += r * sd[k];
            acc[10] += r * vtemp[v * 3 + d];
        }
        __shared__ float red[256];
        for (int k = 0; k < 11; k++) {
            red[t] = acc[k];
            __syncthreads();
            for (int s = 128; s > 0; s >>= 1) {
                if (t < s) red[t] += red[t + s];
                __syncthreads();
            }
            if (t == 0) g_JM[(j * 3 + d) * 11 + k] = red[0];
            __syncthreads();
        }
    } else {
        if (t < 32) {
            int bad = (t < 24 && jmap[2 * t + 1] != 0) ? 1 : 0;
            unsigned m = __ballot_sync(0xffffffff, bad);
            if (t == 0) g_jmap64 = (m == 0) ? 1 : 0;
        }
    }
}

// ============================================================================
// pose: 4 batches per block; rodrigues, chain, Gc; writes bf16 A rows
// ============================================================================
__global__ void __launch_bounds__(128) pose_kernel(const float* __restrict__ pose,
                                                   const float* __restrict__ beta) {
    int w = threadIdx.x >> 5, t = threadIdx.x & 31;
    int b = blockIdx.x * 4 + w;
    __shared__ float sR[4][NJ][9];
    __shared__ float sJ[4][NJ][3];
    __shared__ float sA[4][NJ][12];

    if (t < NJ) {
        float rx = pose[b * 72 + 3 * t + 0];
        float ry = pose[b * 72 + 3 * t + 1];
        float rz = pose[b * 72 + 3 * t + 2];
        float th = sqrtf(rx * rx + ry * ry + rz * rz);
        float inv = 1.f / fmaxf(th, 1e-8f);
        float kx = rx * inv, ky = ry * inv, kz = rz * inv;
        float s = sinf(th), c = cosf(th), C = 1.f - c;
        float kn2 = kx * kx + ky * ky + kz * kz;
        float R[9];
        R[0] = 1.f + C * (kx * kx - kn2);
        R[1] = -s * kz + C * kx * ky;
        R[2] = s * ky + C * kx * kz;
        R[3] = s * kz + C * ky * kx;
        R[4] = 1.f + C * (ky * ky - kn2);
        R[5] = -s * kx + C * ky * kz;
        R[6] = -s * ky + C * kz * kx;
        R[7] = s * kx + C * kz * ky;
        R[8] = 1.f + C * (kz * kz - kn2);
#pragma unroll
        for (int e = 0; e < 9; e++) sR[w][t][e] = R[e];
        if (t >= 1) {
            __nv_bfloat16* dst = g_Ab + b * KDIM + (t - 1) * 9;
#pragma unroll
            for (int e = 0; e < 9; e++) {
                float val = R[e] - ((e == 0 || e == 4 || e == 8) ? 1.f : 0.f);
                dst[e] = __float2bfloat16(val);
            }
        }
#pragma unroll
        for (int d = 0; d < 3; d++) {
            const float* m = g_JM + (t * 3 + d) * 11;
            float val = m[10];
#pragma unroll
            for (int k = 0; k < 10; k++) val += m[k] * beta[b * 10 + k];
            sJ[w][t][d] = val;
        }
    }
    if (t == 0) {
#pragma unroll
        for (int k = 0; k < 10; k++)
            g_Ab[b * KDIM + 207 + k] = __float2bfloat16(beta[b * 10 + k]);
#pragma unroll
        for (int k = 217; k < KDIM; k++)
            g_Ab[b * KDIM + k] = __float2bfloat16(0.f);
    }
    __syncwarp();
    if (t == 0) {
#pragma unroll
        for (int e = 0; e < 9; e++) sA[w][0][(e / 3) * 4 + (e % 3)] = sR[w][0][e];
        sA[w][0][3] = sJ[w][0][0]; sA[w][0][7] = sJ[w][0][1]; sA[w][0][11] = sJ[w][0][2];
        for (int i = 1; i < NJ; i++) {
            int p = c_parent[i - 1];
            float lt0 = sJ[w][i][0] - sJ[w][p][0];
            float lt1 = sJ[w][i][1] - sJ[w][p][1];
            float lt2 = sJ[w][i][2] - sJ[w][p][2];
            for (int r = 0; r < 3; r++) {
                float p0 = sA[w][p][r * 4 + 0], p1 = sA[w][p][r * 4 + 1];
                float p2 = sA[w][p][r * 4 + 2], p3 = sA[w][p][r * 4 + 3];
                for (int cc = 0; cc < 3; cc++)
                    sA[w][i][r * 4 + cc] = p0 * sR[w][i][0 * 3 + cc] + p1 * sR[w][i][1 * 3 + cc] + p2 * sR[w][i][2 * 3 + cc];
                sA[w][i][r * 4 + 3] = p0 * lt0 + p1 * lt1 + p2 * lt2 + p3;
            }
        }
    }
    __syncwarp();
    if (t < NJ) {
        float j0 = sJ[w][t][0], j1 = sJ[w][t][1], j2 = sJ[w][t][2];
        float* dst = g_Gc + (b * NJ + t) * 12;
#pragma unroll
        for (int r = 0; r < 3; r++) {
            float a0 = sA[w][t][r * 4 + 0], a1 = sA[w][t][r * 4 + 1];
            float a2 = sA[w][t][r * 4 + 2], a3 = sA[w][t][r * 4 + 3];
            dst[r * 4 + 0] = a0; dst[r * 4 + 1] = a1; dst[r * 4 + 2] = a2;
            dst[r * 4 + 3] = a3 - (a0 * j0 + a1 * j1 + a2 * j2);
        }
    }
}

// ============================================================================
// GEMM bf16 m16n8k16: v_posed = A @ W^T + vtemp.  KC=32 -> 7 stages (r14 proven).
// ============================================================================
__global__ void __launch_bounds__(256, 2) gemm_bf16_kernel(const float* __restrict__ vtemp) {
    __shared__ __align__(16) __nv_bfloat16 As[2][128][40];
    __shared__ __align__(16) __nv_bfloat16 Bs[2][128][40];
    int tid = threadIdx.x;
    int lane = tid & 31, wid = tid >> 5;
    int warp_m = wid & 1, warp_n = wid >> 1;
    int gq = lane >> 2, tq = lane & 3;
    int m0 = blockIdx.x * 128;
    int n0 = blockIdx.y * 128;

    float acc[4][4][4];
#pragma unroll
    for (int mt = 0; mt < 4; mt++)
#pragma unroll
        for (int nt = 0; nt < 4; nt++)
#pragma unroll
            for (int i = 0; i < 4; i++) acc[mt][nt][i] = 0.f;

    const int NSTAGE = KDIM / KC;  // 7

#define LOAD_STAGE(s, buf)                                                                \
    {                                                                                     \
        int k0 = (s) * KC;                                                                \
        _Pragma("unroll")                                                                 \
        for (int i = 0; i < 2; i++) {                                                     \
            int idx = tid + i * 256;                                                      \
            int row = idx >> 2, ch = idx & 3;                                             \
            unsigned da = (unsigned)__cvta_generic_to_shared(&As[buf][row][ch * 8]);      \
            const __nv_bfloat16* sa = g_Ab + (m0 + row) * KDIM + k0 + ch * 8;             \
            asm volatile("cp.async.cg.shared.global [%0], [%1], 16;" ::"r"(da), "l"(sa)); \
            unsigned db = (unsigned)__cvta_generic_to_shared(&Bs[buf][row][ch * 8]);      \
            const __nv_bfloat16* sb = g_Wb + (size_t)(n0 + row) * KDIM + k0 + ch * 8;     \
            asm volatile("cp.async.cg.shared.global [%0], [%1], 16;" ::"r"(db), "l"(sb)); \
        }                                                                                 \
        asm volatile("cp.async.commit_group;");                                           \
    }

    LOAD_STAGE(0, 0);
    for (int s = 0; s < NSTAGE; s++) {
        int buf = s & 1;
        if (s + 1 < NSTAGE) {
            LOAD_STAGE(s + 1, buf ^ 1);
            asm volatile("cp.async.wait_group 1;");
        } else {
            asm volatile("cp.async.wait_group 0;");
        }
        __syncthreads();
        const uint32_t* As32 = (const uint32_t*)&As[buf][0][0];
        const uint32_t* Bs32 = (const uint32_t*)&Bs[buf][0][0];
#pragma unroll
        for (int kk = 0; kk < 2; kk++) {
            int ko = kk * 8;
            uint32_t af[4][4], bf[4][2];
#pragma unroll
            for (int mt = 0; mt < 4; mt++) {
                int r = warp_m * 64 + mt * 16 + gq;
                af[mt][0] = As32[r * 20 + ko + tq];
                af[mt][1] = As32[(r + 8) * 20 + ko + tq];
                af[mt][2] = As32[r * 20 + ko + 4 + tq];
                af[mt][3] = As32[(r + 8) * 20 + ko + 4 + tq];
            }
#pragma unroll
            for (int nt = 0; nt < 4; nt++) {
                int cn = warp_n * 32 + nt * 8 + gq;
                bf[nt][0] = Bs32[cn * 20 + ko + tq];
                bf[nt][1] = Bs32[cn * 20 + ko + 4 + tq];
            }
#pragma unroll
            for (int mt = 0; mt < 4; mt++)
#pragma unroll
                for (int nt = 0; nt < 4; nt++)
                    mma_bf16(acc[mt][nt], af[mt], bf[nt]);
        }
        __syncthreads();
    }

#pragma unroll
    for (int mt = 0; mt < 4; mt++) {
        int row = m0 + warp_m * 64 + mt * 16 + gq;
#pragma unroll
        for (int nt = 0; nt < 4; nt++) {
            int cn = n0 + warp_n * 32 + nt * 8 + 2 * tq;
            if (cn < N3) {
                float2 vt = *(const float2*)(vtemp + cn);
                float2 o0 = {acc[mt][nt][0] + vt.x, acc[mt][nt][1] + vt.y};
                float2 o1 = {acc[mt][nt][2] + vt.x, acc[mt][nt][3] + vt.y};
                *(float2*)(g_vposed + (size_t)row * N3 + cn) = o0;
                *(float2*)(g_vposed + (size_t)(row + 8) * N3 + cn) = o1;
            }
        }
    }
#undef LOAD_STAGE
}

// ============================================================================
// skin (r11/r14 proven): 2 verts/thread x 16 batches (8 pairs) per block.
// Gc smem fill vectorized: float4 LDG + ulonglong2 STS.
// ============================================================================
__global__ void __launch_bounds__(128) skin_kernel(const float* __restrict__ weights,
                                                   float* __restrict__ out) {
    __shared__ __align__(16) ull sGc2[8 * 288];
    int b0 = blockIdx.y * 16;
    int t = threadIdx.x;
    int vA = blockIdx.x * 256 + t;        // grid.x = 27
    int vB = vA + 128;
    for (int idx = t; idx < 8 * 72; idx += 128) {
        int p = idx / 72, q = idx % 72;
        float4 a = *(const float4*)(g_Gc + (size_t)(b0 + 2 * p) * 288 + q * 4);
        float4 b = *(const float4*)(g_Gc + (size_t)(b0 + 2 * p + 1) * 288 + q * 4);
        ulonglong2* d = (ulonglong2*)(sGc2 + p * 288 + q * 4);
        d[0] = make_ulonglong2(pk2(a.x, b.x), pk2(a.y, b.y));
        d[1] = make_ulonglong2(pk2(a.z, b.z), pk2(a.w, b.w));
    }
    __syncthreads();
    bool okA = vA < NV, okB = vB < NV;
    float wA[NJ], wB[NJ];
    {
        const float4* wa = (const float4*)(weights + (size_t)vA * NJ);
        const float4* wb = (const float4*)(weights + (size_t)vB * NJ);
#pragma unroll
        for (int i = 0; i < 6; i++) {
            float4 x = okA ? wa[i] : make_float4(0.f, 0.f, 0.f, 0.f);
            wA[4 * i + 0] = x.x; wA[4 * i + 1] = x.y; wA[4 * i + 2] = x.z; wA[4 * i + 3] = x.w;
            float4 y = okB ? wb[i] : make_float4(0.f, 0.f, 0.f, 0.f);
            wB[4 * i + 0] = y.x; wB[4 * i + 1] = y.y; wB[4 * i + 2] = y.z; wB[4 * i + 3] = y.w;
        }
    }
    float curA[6], curB[6], nxtA[6], nxtB[6];
#pragma unroll
    for (int i = 0; i < 6; i++) { curA[i] = 0.f; curB[i] = 0.f; nxtA[i] = 0.f; nxtB[i] = 0.f; }
    {
        const float* va = g_vposed + (size_t)b0 * N3;
        const float* vb = va + N3;
        if (okA) {
            curA[0] = va[vA * 3 + 0]; curA[1] = va[vA * 3 + 1]; curA[2] = va[vA * 3 + 2];
            curA[3] = vb[vA * 3 + 0]; curA[4] = vb[vA * 3 + 1]; curA[5] = vb[vA * 3 + 2];
        }
        if (okB) {
            curB[0] = va[vB * 3 + 0]; curB[1] = va[vB * 3 + 1]; curB[2] = va[vB * 3 + 2];
            curB[3] = vb[vB * 3 + 0]; curB[4] = vb[vB * 3 + 1]; curB[5] = vb[vB * 3 + 2];
        }
    }
#pragma unroll 1
    for (int p = 0; p < 8; p++) {
        if (p < 7) {
            const float* va = g_vposed + (size_t)(b0 + 2 * p + 2) * N3;
            const float* vb = va + N3;
            if (okA) {
                nxtA[0] = va[vA * 3 + 0]; nxtA[1] = va[vA * 3 + 1]; nxtA[2] = va[vA * 3 + 2];
                nxtA[3] = vb[vA * 3 + 0]; nxtA[4] = vb[vA * 3 + 1]; nxtA[5] = vb[vA * 3 + 2];
            }
            if (okB) {
                nxtB[0] = va[vB * 3 + 0]; nxtB[1] = va[vB * 3 + 1]; nxtB[2] = va[vB * 3 + 2];
                nxtB[3] = vb[vB * 3 + 0]; nxtB[4] = vb[vB * 3 + 1]; nxtB[5] = vb[vB * 3 + 2];
            }
        }
        ull TA[12], TB[12];
#pragma unroll
        for (int c = 0; c < 12; c++) { TA[c] = 0ull; TB[c] = 0ull; }
        const ulonglong2* gc = (const ulonglong2*)(sGc2 + p * 288);
#pragma unroll
        for (int j = 0; j < NJ; j++) {
            ull wa2 = pk2(wA[j], wA[j]);
            ull wb2 = pk2(wB[j], wB[j]);
#pragma unroll
            for (int i = 0; i < 6; i++) {
                ulonglong2 g2 = gc[j * 6 + i];
                TA[2 * i + 0] = ffma2(wa2, g2.x, TA[2 * i + 0]);
                TA[2 * i + 1] = ffma2(wa2, g2.y, TA[2 * i + 1]);
                TB[2 * i + 0] = ffma2(wb2, g2.x, TB[2 * i + 0]);
                TB[2 * i + 1] = ffma2(wb2, g2.y, TB[2 * i + 1]);
            }
        }
        int ba = b0 + 2 * p, bb = ba + 1;
        if (okA) {
            ull px = pk2(curA[0], curA[3]);
            ull py = pk2(curA[1], curA[4]);
            ull pz = pk2(curA[2], curA[5]);
            float* oa = out + (size_t)ba * N3 + vA * 3;
            float* ob = out + (size_t)bb * N3 + vA * 3;
#pragma unroll
            for (int r = 0; r < 3; r++) {
                ull o2 = ffma2(TA[4 * r + 0], px,
                         ffma2(TA[4 * r + 1], py,
                         ffma2(TA[4 * r + 2], pz, TA[4 * r + 3])));
                float xa, xb;
                upk2(o2, xa, xb);
                oa[r] = xa; ob[r] = xb;
            }
        }
        if (okB) {
            ull px = pk2(curB[0], curB[3]);
            ull py = pk2(curB[1], curB[4]);
            ull pz = pk2(curB[2], curB[5]);
            float* oa = out + (size_t)ba * N3 + vB * 3;
            float* ob = out + (size_t)bb * N3 + vB * 3;
#pragma unroll
            for (int r = 0; r < 3; r++) {
                ull o2 = ffma2(TB[4 * r + 0], px,
                         ffma2(TB[4 * r + 1], py,
                         ffma2(TB[4 * r + 2], pz, TB[4 * r + 3])));
                float xa, xb;
                upk2(o2, xa, xb);
                oa[r] = xa; ob[r] = xb;
            }
        }
#pragma unroll
        for (int i = 0; i < 6; i++) { curA[i] = nxtA[i]; curB[i] = nxtB[i]; }
    }
}

// ============================================================================
// joints (r14 proven): 32 batches/block (16 pairs), 4 joints/thread,
// grid (16, 32), reg-prefetch pipeline, float sreg + per-iter pk2.
// ============================================================================
__global__ void __launch_bounds__(256) joints_kernel(const float* __restrict__ Jreg,
                                                     const float* __restrict__ Jspin,
                                                     const float* __restrict__ Jextra,
                                                     const float* __restrict__ outv) {
    __shared__ __align__(16) float sreg[32 * 68];
    __shared__ __align__(16) ull sv2[32 * 48];
    float* svh = (float*)sv2;
    int b0 = blockIdx.x * 32;   // grid.x = 16
    int seg = blockIdx.y;       // grid.y = 32
    int tid = threadIdx.x;
    int tx = tid & 15, ty = tid >> 4;
    int j0 = ty * 4;
    ull acc2[4][3];
#pragma unroll
    for (int i = 0; i < 4; i++)
#pragma unroll
        for (int d = 0; d < 3; d++) acc2[i][d] = 0ull;

    float rga[8];
    float2 sva[6];
    int kbeg = seg * SEGLEN;

#define PREFETCH_TILE(k0)                                                        \
    {                                                                            \
        _Pragma("unroll")                                                        \
        for (int i = 0; i < 8; i++) {                                            \
            int idx = tid + i * 256;                                             \
            int j = idx >> 5, vv = idx & 31;                                     \
            int gk = (k0) + vv;                                                  \
            float val = 0.f;                                                     \
            if (j < J54 && gk < NV) val = reg_row(j, Jreg, Jspin, Jextra)[gk];   \
            rga[i] = val;                                                        \
        }                                                                        \
        _Pragma("unroll")                                                        \
        for (int q = 0; q < 6; q++) {                                            \
            int idx = tid + q * 256;                                             \
            int pr = idx / 96, e = idx % 96;                                     \
            int half = e / 48, r2 = e % 48;                                      \
            sva[q] = *(const float2*)(outv + (size_t)(b0 + 2 * pr + half) * N3   \
                                       + (k0) * 3 + r2 * 2);                     \
        }                                                                        \
    }

#define COMMIT_TILE()                                                            \
    {                                                                            \
        _Pragma("unroll")                                                        \
        for (int i = 0; i < 8; i++) {                                            \
            int idx = tid + i * 256;                                             \
            sreg[(idx & 31) * 68 + (idx >> 5)] = rga[i];                         \
        }                                                                        \
        _Pragma("unroll")                                                        \
        for (int q = 0; q < 6; q++) {                                            \
            int idx = tid + q * 256;                                             \
            int pr = idx / 96, e = idx % 96;                                     \
            int half = e / 48, r2 = e % 48;                                      \
            int rem = r2 * 2;                                                    \
            int f0 = rem / 3, d0 = rem % 3;                                      \
            int f1 = (rem + 1) / 3, d1 = (rem + 1) % 3;                          \
            svh[(f0 * 48 + pr * 3 + d0) * 2 + half] = sva[q].x;                  \
            svh[(f1 * 48 + pr * 3 + d1) * 2 + half] = sva[q].y;                  \
        }                                                                        \
    }

    PREFETCH_TILE(kbeg);

    for (int k0 = kbeg; k0 < kbeg + SEGLEN; k0 += 32) {
        COMMIT_TILE();
        __syncthreads();
        int kn = k0 + 32;
        if (kn < kbeg + SEGLEN) PREFETCH_TILE(kn);
#pragma unroll
        for (int vv = 0; vv < 32; vv++) {
            float4 a = *(const float4*)&sreg[vv * 68 + j0];
            ull a0 = pk2(a.x, a.x), a1 = pk2(a.y, a.y);
            ull a2 = pk2(a.z, a.z), a3 = pk2(a.w, a.w);
            ull bx = sv2[vv * 48 + tx * 3 + 0];
            ull by = sv2[vv * 48 + tx * 3 + 1];
            ull bz = sv2[vv * 48 + tx * 3 + 2];
            acc2[0][0] = ffma2(a0, bx, acc2[0][0]);
            acc2[0][1] = ffma2(a0, by, acc2[0][1]);
            acc2[0][2] = ffma2(a0, bz, acc2[0][2]);
            acc2[1][0] = ffma2(a1, bx, acc2[1][0]);
            acc2[1][1] = ffma2(a1, by, acc2[1][1]);
            acc2[1][2] = ffma2(a1, bz, acc2[1][2]);
            acc2[2][0] = ffma2(a2, bx, acc2[2][0]);
            acc2[2][1] = ffma2(a2, by, acc2[2][1]);
            acc2[2][2] = ffma2(a2, bz, acc2[2][2]);
            acc2[3][0] = ffma2(a3, bx, acc2[3][0]);
            acc2[3][1] = ffma2(a3, by, acc2[3][1]);
            acc2[3][2] = ffma2(a3, bz, acc2[3][2]);
        }
        __syncthreads();
    }
#undef PREFETCH_TILE
#undef COMMIT_TILE

    int ba = b0 + 2 * tx, bb2 = ba + 1;
#pragma unroll
    for (int i = 0; i < 4; i++) {
        int j = j0 + i;
        if (j < J54) {
#pragma unroll
            for (int d = 0; d < 3; d++) {
                float xa, xb;
                upk2(acc2[i][d], xa, xb);
                g_part[((size_t)(seg * BATCH + ba) * J54 + j) * 3 + d] = xa;
                g_part[((size_t)(seg * BATCH + bb2) * J54 + j) * 3 + d] = xb;
            }
        }
    }
}

// ============================================================================
// finalize: sum partials, pelvis, write joints & pelvis, shift vertices.
// 512 threads for more streaming parallelism in the shift loop.
// ============================================================================
__global__ void __launch_bounds__(512) finalize_kernel(const int* __restrict__ jmap,
                                                       float* __restrict__ out) {
    int b = blockIdx.x, t = threadIdx.x;
    __shared__ float jall[J54 * 3];
    __shared__ float pel[3];
    int is64 = g_jmap64;
    if (t < 162) {
        float s = 0.f;
        for (int seg = 0; seg < NSEG; seg++)
            s += g_part[(size_t)(seg * BATCH + b) * (J54 * 3) + t];
        jall[t] = s;
    }
    __syncthreads();
    if (t < 3) {
        int a = is64 ? jmap[2 * 27] : jmap[27];
        int c = is64 ? jmap[2 * 28] : jmap[28];
        float p = 0.5f * (jall[a * 3 + t] + jall[c * 3 + t]);
        pel[t] = p;
        out[(size_t)BATCH * N3 + (size_t)BATCH * 147 + b * 3 + t] = p;
    }
    __syncthreads();
    if (t < 147) {
        int i = t / 3, d = t % 3;
        int j = is64 ? jmap[2 * i] : jmap[i];
        out[(size_t)BATCH * N3 + b * 147 + t] = jall[j * 3 + d] - pel[d];
    }
    float p0 = pel[0], p1 = pel[1], p2 = pel[2];
    float* vb = out + (size_t)b * N3;
    for (int p = t; p < N3 / 2; p += 512) {
        int idx = 2 * p;
        int d0 = idx % 3;
        float2 v = *(float2*)(vb + idx);
        v.x -= (d0 == 0) ? p0 : (d0 == 1) ? p1 : p2;
        int d1 = (d0 + 1 == 3) ? 0 : d0 + 1;
        v.y -= (d1 == 0) ? p0 : (d1 == 1) ? p1 : p2;
        *(float2*)(vb + idx) = v;
    }
}

// ============================================================================
extern "C" void kernel_launch(void* const* d_in, const int* in_sizes, int n_in,
                              void* d_out, int out_size) {
    const float* pose      = (const float*)d_in[0];
    const float* beta      = (const float*)d_in[1];
    const float* vtemp     = (const float*)d_in[2];
    const float* shapedirs = (const float*)d_in[3];
    const float* posedirs  = (const float*)d_in[4];
    const float* weights   = (const float*)d_in[5];
    const float* Jreg      = (const float*)d_in[6];
    const float* Jspin     = (const float*)d_in[7];
    const float* Jextra    = (const float*)d_in[8];
    const int* jmap        = (const int*)d_in[10];
    float* out = (float*)d_out;

    prep_kernel<<<NP / 8 + 73, 256>>>(posedirs, shapedirs, Jreg, vtemp, jmap); // 0
    pose_kernel<<<BATCH / 4, 128>>>(pose, beta);                               // 1
    gemm_bf16_kernel<<<dim3(BATCH / 128, NP / 128), 256>>>(vtemp);             // 2
    skin_kernel<<<dim3(27, BATCH / 16), 128>>>(weights, out);                  // 3 <- profiled
    joints_kernel<<<dim3(BATCH / 32, NSEG), 256>>>(Jreg, Jspin, Jextra, out);  // 4
    finalize_kernel<<<BATCH, 512>>>(jmap, out);                                // 5
}